// round 10
// baseline (speedup 1.0000x reference)
#include <cuda_runtime.h>

// Shape fixed by reference setup_inputs
#define B_  16
#define C_  64
#define H_  64
#define W_  64
#define T_  32
#define HP_ 32
#define WP_ 32

#define NBLK   (B_ * C_ * (HP_ / 4))   // 8192 logical tiles
#define GRIDSZ (148 * 12)              // persistent: ~1 resident wave

// Tile blk (= bc*8 + g) is CONTIGUOUS in both input and output:
//   input  float4 range: [blk*4096, blk*4096 + 4096)   (8 rows x 512 f4)
//   output float4 range: [blk*1024, blk*1024 + 1024)   (128 pixels x 8 f4)
// Warp w owns pooled row hl=w (input rows 2w, 2w+1 of the tile).
// smem (float4 units): row r (0..127), chunk c (0..7) at r*8 + (c ^ (r&7)).
__global__ void __launch_bounds__(128, 12) savgpool_spike_kernel(
    const float* __restrict__ x,
    const float* __restrict__ thresh,
    float* __restrict__ out)
{
    __shared__ float4 sp[128 * 8];      // 16 KB

    const int t    = threadIdx.x;
    const int lane = t & 31;
    const int w    = t >> 5;

    const float th = __ldg(thresh);
    const float4* __restrict__ x4 = (const float4*)x;
    float4* __restrict__ o4       = (float4*)out;

    for (int blk = blockIdx.x; blk < NBLK; blk += GRIDSZ) {
        const float4* __restrict__ xt = x4 + (size_t)blk * 4096 + (2 * w) * 512;
        float4* __restrict__ ot       = o4 + (size_t)blk * 1024 + w * 256;

        // ---- Phase 1: 2x2 pool -> swizzled smem (STS.128) ----
        #pragma unroll
        for (int it = 0; it < 8; it++) {
            int idx = it * 32 + lane;       // 0..255
            int wp  = idx >> 3;
            int c   = idx & 7;
            const float4* p0 = xt + (2 * wp) * 8 + c;
            float4 a  = __ldcs(p0);
            float4 b  = __ldcs(p0 + 8);     // w-pair partner
            float4 cc = __ldcs(p0 + 512);   // next h row
            float4 d  = __ldcs(p0 + 520);
            int r = w * 32 + wp;
            float4 v;
            v.x = (a.x + b.x + cc.x + d.x) * 0.25f;
            v.y = (a.y + b.y + cc.y + d.y) * 0.25f;
            v.z = (a.z + b.z + cc.z + d.z) * 0.25f;
            v.w = (a.w + b.w + cc.w + d.w) * 0.25f;
            sp[r * 8 + (c ^ (r & 7))] = v;
        }
        __syncwarp();

        // ---- Phase 2: LIF recurrence in float4 groups (LDS.128/STS.128) ----
        {
            const int sw = t & 7;
            float4* row = &sp[t * 8];
            float u = 0.0f, s = 0.0f;
            #pragma unroll
            for (int c = 0; c < 8; c++) {
                float4 q = row[c ^ sw];
                float4 v;
                u = u - s * th + q.x;  s = (u > 0.0f) ? 1.0f : 0.0f;  v.x = s;
                u = u - s * th + q.y;  s = (u > 0.0f) ? 1.0f : 0.0f;  v.y = s;
                u = u - s * th + q.z;  s = (u > 0.0f) ? 1.0f : 0.0f;  v.z = s;
                u = u - s * th + q.w;  s = (u > 0.0f) ? 1.0f : 0.0f;  v.w = s;
                row[c ^ sw] = v;
            }
        }
        __syncwarp();

        // ---- Phase 3: coalesced float4 write-out (LDS.128 -> STG.128) ----
        #pragma unroll
        for (int it = 0; it < 8; it++) {
            int cl = it * 32 + lane;        // 0..255 within warp's span
            int r  = w * 32 + (cl >> 3);
            int c  = cl & 7;
            __stcs(ot + cl, sp[r * 8 + (c ^ (r & 7))]);
        }
        __syncwarp();                       // protect smem before next tile
    }
}

extern "C" void kernel_launch(void* const* d_in, const int* in_sizes, int n_in,
                              void* d_out, int out_size)
{
    const float* x      = (const float*)d_in[0];
    const float* thresh = (const float*)d_in[1];
    float* out          = (float*)d_out;

    savgpool_spike_kernel<<<GRIDSZ, 128>>>(x, thresh, out);
}

// round 11
// speedup vs baseline: 1.2282x; 1.2282x over previous
#include <cuda_runtime.h>

// Shape fixed by reference setup_inputs
#define B_  16
#define C_  64
#define H_  64
#define W_  64
#define T_  32
#define HP_ 32
#define WP_ 32

#define NBLK   (B_ * C_ * (HP_ / 4))   // 8192 logical tiles
#define GRIDSZ (148 * 12)              // 1776: 12 blocks per SM, dynamic drain

// Tile blk is CONTIGUOUS in both input and output:
//   input  float4 range: [blk*4096, blk*4096 + 4096)   (8 rows x 512 f4)
//   output float4 range: [blk*1024, blk*1024 + 1024)   (128 pixels x 8 f4)
// Warp w owns pooled row hl=w (input rows 2w, 2w+1 of the tile).
// smem (float4 units): row r (0..127), chunk c (0..7) at r*8 + (c ^ (r&7)).
//
// NO occupancy cap: the compiler's natural ~54-reg allocation front-batches
// the phase-1 loads (high per-thread MLP). R9 proved capping regs to raise
// occupancy collapses MLP and loses 28 us.
__global__ void __launch_bounds__(128) savgpool_spike_kernel(
    const float* __restrict__ x,
    const float* __restrict__ thresh,
    float* __restrict__ out)
{
    __shared__ float4 sp[128 * 8];      // 16 KB

    const int t    = threadIdx.x;
    const int lane = t & 31;
    const int w    = t >> 5;

    const float th = __ldg(thresh);
    const float4* __restrict__ x4 = (const float4*)x;
    float4* __restrict__ o4       = (float4*)out;

    for (int blk = blockIdx.x; blk < NBLK; blk += GRIDSZ) {
        const float4* __restrict__ xt = x4 + (size_t)blk * 4096 + (2 * w) * 512;
        float4* __restrict__ ot       = o4 + (size_t)blk * 1024 + w * 256;

        // ---- Phase 1: 2x2 pool -> swizzled smem (STS.128) ----
        #pragma unroll
        for (int it = 0; it < 8; it++) {
            int idx = it * 32 + lane;       // 0..255
            int wp  = idx >> 3;
            int c   = idx & 7;
            const float4* p0 = xt + (2 * wp) * 8 + c;
            float4 a  = __ldcs(p0);
            float4 b  = __ldcs(p0 + 8);     // w-pair partner
            float4 cc = __ldcs(p0 + 512);   // next h row
            float4 d  = __ldcs(p0 + 520);
            int r = w * 32 + wp;
            float4 v;
            v.x = (a.x + b.x + cc.x + d.x) * 0.25f;
            v.y = (a.y + b.y + cc.y + d.y) * 0.25f;
            v.z = (a.z + b.z + cc.z + d.z) * 0.25f;
            v.w = (a.w + b.w + cc.w + d.w) * 0.25f;
            sp[r * 8 + (c ^ (r & 7))] = v;
        }
        __syncwarp();

        // ---- Phase 2: LIF recurrence in float4 groups (LDS.128/STS.128) ----
        {
            const int sw = t & 7;
            float4* row = &sp[t * 8];
            float u = 0.0f, s = 0.0f;
            #pragma unroll
            for (int c = 0; c < 8; c++) {
                float4 q = row[c ^ sw];
                float4 v;
                u = u - s * th + q.x;  s = (u > 0.0f) ? 1.0f : 0.0f;  v.x = s;
                u = u - s * th + q.y;  s = (u > 0.0f) ? 1.0f : 0.0f;  v.y = s;
                u = u - s * th + q.z;  s = (u > 0.0f) ? 1.0f : 0.0f;  v.z = s;
                u = u - s * th + q.w;  s = (u > 0.0f) ? 1.0f : 0.0f;  v.w = s;
                row[c ^ sw] = v;
            }
        }
        __syncwarp();

        // ---- Phase 3: coalesced float4 write-out (LDS.128 -> STG.128) ----
        #pragma unroll
        for (int it = 0; it < 8; it++) {
            int cl = it * 32 + lane;        // 0..255 within warp's span
            int r  = w * 32 + (cl >> 3);
            int c  = cl & 7;
            __stcs(ot + cl, sp[r * 8 + (c ^ (r & 7))]);
        }
        __syncwarp();                       // protect smem before next tile
    }
}

extern "C" void kernel_launch(void* const* d_in, const int* in_sizes, int n_in,
                              void* d_out, int out_size)
{
    const float* x      = (const float*)d_in[0];
    const float* thresh = (const float*)d_in[1];
    float* out          = (float*)d_out;

    savgpool_spike_kernel<<<GRIDSZ, 128>>>(x, thresh, out);
}

// round 12
// speedup vs baseline: 1.3165x; 1.0719x over previous
#include <cuda_runtime.h>

// Shape fixed by reference setup_inputs
#define B_  16
#define C_  64
#define H_  64
#define W_  64
#define T_  32
#define HP_ 32
#define WP_ 32

#define NBLK   (B_ * C_ * (HP_ / 4))   // 8192 logical tiles
#define GRIDSZ (148 * 10)              // >= resident CTAs; extras exit fast

// Dynamic tile counter: zeroed by init kernel at the start of every
// kernel_launch call (both part of the captured graph -> deterministic).
__device__ unsigned int g_tile_ctr;

__global__ void reset_ctr_kernel() { g_tile_ctr = 0u; }

// Tile blk is CONTIGUOUS in both input and output:
//   input  float4 range: [blk*4096, blk*4096 + 4096)   (8 rows x 512 f4)
//   output float4 range: [blk*1024, blk*1024 + 1024)   (128 pixels x 8 f4)
// Warp w owns pooled row hl=w (input rows 2w, 2w+1 of the tile).
// smem (float4 units): row r (0..127), chunk c (0..7) at r*8 + (c ^ (r&7)).
//
// Phase 1 issues 8 LDG.128 back-to-back (two pooled chunks) before consuming:
// explicit deep MLP — R8/R9/R10 showed DRAM% tracks load batching depth.
__global__ void __launch_bounds__(128) savgpool_spike_kernel(
    const float* __restrict__ x,
    const float* __restrict__ thresh,
    float* __restrict__ out)
{
    __shared__ float4 sp[128 * 8];      // 16 KB

    const int t    = threadIdx.x;
    const int lane = t & 31;
    const int w    = t >> 5;

    const float th = __ldg(thresh);
    const float4* __restrict__ x4 = (const float4*)x;
    float4* __restrict__ o4       = (float4*)out;

    for (;;) {
        unsigned int blk;
        if (lane == 0 && w == 0) blk = atomicAdd(&g_tile_ctr, 1u);
        blk = __shfl_sync(0xffffffffu, blk, 0);
        // broadcast across warps via smem would need a barrier; instead each
        // warp grabs independently? No: one counter bump per BLOCK, lane0 of
        // warp0 got it — share via smem once.
        __shared__ unsigned int s_blk;
        if (t == 0) s_blk = blk;
        __syncthreads();
        blk = s_blk;
        if (blk >= NBLK) break;

        const float4* __restrict__ xt = x4 + (size_t)blk * 4096 + (2 * w) * 512;
        float4* __restrict__ ot       = o4 + (size_t)blk * 1024 + w * 256;

        // ---- Phase 1: 2x2 pool -> swizzled smem; 8 loads in flight ----
        #pragma unroll
        for (int it2 = 0; it2 < 4; it2++) {
            int idx0 = (2 * it2) * 32 + lane;       // 0..255
            int idx1 = idx0 + 32;
            int wp0 = idx0 >> 3, c0 = idx0 & 7;
            int wp1 = idx1 >> 3, c1 = idx1 & 7;
            const float4* p0 = xt + (2 * wp0) * 8 + c0;
            const float4* p1 = xt + (2 * wp1) * 8 + c1;
            // 8 back-to-back LDG.128 (512B-contiguous per warp each)
            float4 a0 = __ldcs(p0);
            float4 b0 = __ldcs(p0 + 8);
            float4 e0 = __ldcs(p0 + 512);
            float4 d0 = __ldcs(p0 + 520);
            float4 a1 = __ldcs(p1);
            float4 b1 = __ldcs(p1 + 8);
            float4 e1 = __ldcs(p1 + 512);
            float4 d1 = __ldcs(p1 + 520);

            int r0 = w * 32 + wp0;
            int r1 = w * 32 + wp1;
            float4 v0, v1;
            v0.x = (a0.x + b0.x + e0.x + d0.x) * 0.25f;
            v0.y = (a0.y + b0.y + e0.y + d0.y) * 0.25f;
            v0.z = (a0.z + b0.z + e0.z + d0.z) * 0.25f;
            v0.w = (a0.w + b0.w + e0.w + d0.w) * 0.25f;
            v1.x = (a1.x + b1.x + e1.x + d1.x) * 0.25f;
            v1.y = (a1.y + b1.y + e1.y + d1.y) * 0.25f;
            v1.z = (a1.z + b1.z + e1.z + d1.z) * 0.25f;
            v1.w = (a1.w + b1.w + e1.w + d1.w) * 0.25f;
            sp[r0 * 8 + (c0 ^ (r0 & 7))] = v0;
            sp[r1 * 8 + (c1 ^ (r1 & 7))] = v1;
        }
        __syncwarp();

        // ---- Phase 2: LIF recurrence in float4 groups (LDS.128/STS.128) ----
        {
            const int sw = t & 7;
            float4* row = &sp[t * 8];
            float u = 0.0f, s = 0.0f;
            #pragma unroll
            for (int c = 0; c < 8; c++) {
                float4 q = row[c ^ sw];
                float4 v;
                u = u - s * th + q.x;  s = (u > 0.0f) ? 1.0f : 0.0f;  v.x = s;
                u = u - s * th + q.y;  s = (u > 0.0f) ? 1.0f : 0.0f;  v.y = s;
                u = u - s * th + q.z;  s = (u > 0.0f) ? 1.0f : 0.0f;  v.z = s;
                u = u - s * th + q.w;  s = (u > 0.0f) ? 1.0f : 0.0f;  v.w = s;
                row[c ^ sw] = v;
            }
        }
        __syncwarp();

        // ---- Phase 3: coalesced float4 write-out (LDS.128 -> STG.128) ----
        #pragma unroll
        for (int it = 0; it < 8; it++) {
            int cl = it * 32 + lane;        // 0..255 within warp's span
            int r  = w * 32 + (cl >> 3);
            int c  = cl & 7;
            __stcs(ot + cl, sp[r * 8 + (c ^ (r & 7))]);
        }
        __syncthreads();                    // smem reuse + s_blk ordering
    }
}

extern "C" void kernel_launch(void* const* d_in, const int* in_sizes, int n_in,
                              void* d_out, int out_size)
{
    const float* x      = (const float*)d_in[0];
    const float* thresh = (const float*)d_in[1];
    float* out          = (float*)d_out;

    reset_ctr_kernel<<<1, 1>>>();
    savgpool_spike_kernel<<<GRIDSZ, 128>>>(x, thresh, out);
}

// round 13
// speedup vs baseline: 1.3206x; 1.0031x over previous
#include <cuda_runtime.h>
#include <cuda.h>

// Shape fixed by reference setup_inputs
#define NBLK   8192                    // tiles; tile = 8 input rows / 128 out pixels
#define GRIDSZ (148 * 10)

__device__ unsigned int g_tile_ctr;
__global__ void reset_ctr_kernel() { g_tile_ctr = 0u; }

__device__ __forceinline__ unsigned int smem_u32(const void* p) {
    return (unsigned int)__cvta_generic_to_shared(p);
}

// ---------------- TMA-store version ----------------
// Tile blk contiguous in input ([blk*4096, +4096) float4) and output
// ([blk*1024, +1024) float4). Warp w owns pooled row hl=w.
// smem (float4 units): row r, chunk c at r*8 + (c ^ (r&7))  == TMA SW128 atom.
__global__ void __launch_bounds__(128) savgpool_spike_tma(
    const float* __restrict__ x,
    const float* __restrict__ thresh,
    const __grid_constant__ CUtensorMap tmap)
{
    __shared__ __align__(1024) float4 sp[128 * 8];   // 16 KB
    __shared__ unsigned int s_blk;

    const int t    = threadIdx.x;
    const int lane = t & 31;
    const int w    = t >> 5;
    const float th = __ldg(thresh);
    const float4* __restrict__ x4 = (const float4*)x;

    if (t == 0) s_blk = atomicAdd(&g_tile_ctr, 1u);
    __syncthreads();
    unsigned int blk = s_blk;

    while (blk < NBLK) {
        const float4* __restrict__ xt = x4 + (size_t)blk * 4096 + (2 * w) * 512;

        // ---- batch 0: issue 8 LDG.128 BEFORE the smem-reuse wait ----
        int wp0 = lane >> 3, c0 = lane & 7;
        int wp1 = wp0 + 4;
        const float4* p0 = xt + (2 * wp0) * 8 + c0;
        const float4* p1 = xt + (2 * wp1) * 8 + c0;
        float4 a0 = __ldcs(p0), b0 = __ldcs(p0 + 8);
        float4 e0 = __ldcs(p0 + 512), d0 = __ldcs(p0 + 520);
        float4 a1 = __ldcs(p1), b1 = __ldcs(p1 + 8);
        float4 e1 = __ldcs(p1 + 512), d1 = __ldcs(p1 + 520);

        // previous tile's TMA store must finish READING smem before any STS
        if (t == 0)
            asm volatile("cp.async.bulk.wait_group.read 0;" ::: "memory");
        __syncthreads();

        {
            int r0 = w * 32 + wp0, r1 = w * 32 + wp1;
            float4 v0, v1;
            v0.x = (a0.x + b0.x + e0.x + d0.x) * 0.25f;
            v0.y = (a0.y + b0.y + e0.y + d0.y) * 0.25f;
            v0.z = (a0.z + b0.z + e0.z + d0.z) * 0.25f;
            v0.w = (a0.w + b0.w + e0.w + d0.w) * 0.25f;
            v1.x = (a1.x + b1.x + e1.x + d1.x) * 0.25f;
            v1.y = (a1.y + b1.y + e1.y + d1.y) * 0.25f;
            v1.z = (a1.z + b1.z + e1.z + d1.z) * 0.25f;
            v1.w = (a1.w + b1.w + e1.w + d1.w) * 0.25f;
            sp[r0 * 8 + (c0 ^ (r0 & 7))] = v0;
            sp[r1 * 8 + (c0 ^ (r1 & 7))] = v1;
        }

        // ---- batches 1..3 ----
        #pragma unroll
        for (int it2 = 1; it2 < 4; it2++) {
            int idx0 = (2 * it2) * 32 + lane;
            int idx1 = idx0 + 32;
            int wq0 = idx0 >> 3, cq0 = idx0 & 7;
            int wq1 = idx1 >> 3, cq1 = idx1 & 7;
            const float4* q0 = xt + (2 * wq0) * 8 + cq0;
            const float4* q1 = xt + (2 * wq1) * 8 + cq1;
            float4 ax0 = __ldcs(q0), bx0 = __ldcs(q0 + 8);
            float4 ex0 = __ldcs(q0 + 512), dx0 = __ldcs(q0 + 520);
            float4 ax1 = __ldcs(q1), bx1 = __ldcs(q1 + 8);
            float4 ex1 = __ldcs(q1 + 512), dx1 = __ldcs(q1 + 520);
            int r0 = w * 32 + wq0, r1 = w * 32 + wq1;
            float4 v0, v1;
            v0.x = (ax0.x + bx0.x + ex0.x + dx0.x) * 0.25f;
            v0.y = (ax0.y + bx0.y + ex0.y + dx0.y) * 0.25f;
            v0.z = (ax0.z + bx0.z + ex0.z + dx0.z) * 0.25f;
            v0.w = (ax0.w + bx0.w + ex0.w + dx0.w) * 0.25f;
            v1.x = (ax1.x + bx1.x + ex1.x + dx1.x) * 0.25f;
            v1.y = (ax1.y + bx1.y + ex1.y + dx1.y) * 0.25f;
            v1.z = (ax1.z + bx1.z + ex1.z + dx1.z) * 0.25f;
            v1.w = (ax1.w + bx1.w + ex1.w + dx1.w) * 0.25f;
            sp[r0 * 8 + (cq0 ^ (r0 & 7))] = v0;
            sp[r1 * 8 + (cq1 ^ (r1 & 7))] = v1;
        }
        __syncwarp();

        // ---- phase 2: LIF recurrence in place (own row) ----
        {
            const int sw = t & 7;
            float4* row = &sp[t * 8];
            float u = 0.0f, s = 0.0f;
            #pragma unroll
            for (int c = 0; c < 8; c++) {
                float4 q = row[c ^ sw];
                float4 v;
                u = u - s * th + q.x;  s = (u > 0.0f) ? 1.0f : 0.0f;  v.x = s;
                u = u - s * th + q.y;  s = (u > 0.0f) ? 1.0f : 0.0f;  v.y = s;
                u = u - s * th + q.z;  s = (u > 0.0f) ? 1.0f : 0.0f;  v.z = s;
                u = u - s * th + q.w;  s = (u > 0.0f) ? 1.0f : 0.0f;  v.w = s;
                row[c ^ sw] = v;
            }
        }
        asm volatile("fence.proxy.async.shared::cta;" ::: "memory");

        if (t == 0) s_blk = atomicAdd(&g_tile_ctr, 1u);   // prefetch next tile
        __syncthreads();          // spikes + s_blk visible everywhere

        if (t == 0) {
            asm volatile(
                "cp.async.bulk.tensor.2d.global.shared::cta.tile.bulk_group "
                "[%0, {%1, %2}], [%3];"
                :: "l"(&tmap), "r"(0), "r"((int)(blk * 128)), "r"(smem_u32(sp))
                : "memory");
            asm volatile("cp.async.bulk.commit_group;" ::: "memory");
        }
        blk = s_blk;
    }
    if (t == 0)
        asm volatile("cp.async.bulk.wait_group 0;" ::: "memory");  // drain
}

// ---------------- Fallback (R11, proven 103.2us) ----------------
__global__ void __launch_bounds__(128) savgpool_spike_fb(
    const float* __restrict__ x,
    const float* __restrict__ thresh,
    float* __restrict__ out)
{
    __shared__ float4 sp[128 * 8];
    __shared__ unsigned int s_blk;
    const int t = threadIdx.x, lane = t & 31, w = t >> 5;
    const float th = __ldg(thresh);
    const float4* __restrict__ x4 = (const float4*)x;
    float4* __restrict__ o4 = (float4*)out;

    for (;;) {
        if (t == 0) s_blk = atomicAdd(&g_tile_ctr, 1u);
        __syncthreads();
        unsigned int blk = s_blk;
        if (blk >= NBLK) break;
        const float4* __restrict__ xt = x4 + (size_t)blk * 4096 + (2 * w) * 512;
        float4* __restrict__ ot = o4 + (size_t)blk * 1024 + w * 256;
        #pragma unroll
        for (int it2 = 0; it2 < 4; it2++) {
            int idx0 = (2 * it2) * 32 + lane, idx1 = idx0 + 32;
            int wp0 = idx0 >> 3, cc0 = idx0 & 7, wp1 = idx1 >> 3, cc1 = idx1 & 7;
            const float4* p0 = xt + (2 * wp0) * 8 + cc0;
            const float4* p1 = xt + (2 * wp1) * 8 + cc1;
            float4 a0 = __ldcs(p0), b0 = __ldcs(p0 + 8), e0 = __ldcs(p0 + 512), d0 = __ldcs(p0 + 520);
            float4 a1 = __ldcs(p1), b1 = __ldcs(p1 + 8), e1 = __ldcs(p1 + 512), d1 = __ldcs(p1 + 520);
            int r0 = w * 32 + wp0, r1 = w * 32 + wp1;
            float4 v0, v1;
            v0.x = (a0.x+b0.x+e0.x+d0.x)*0.25f; v0.y = (a0.y+b0.y+e0.y+d0.y)*0.25f;
            v0.z = (a0.z+b0.z+e0.z+d0.z)*0.25f; v0.w = (a0.w+b0.w+e0.w+d0.w)*0.25f;
            v1.x = (a1.x+b1.x+e1.x+d1.x)*0.25f; v1.y = (a1.y+b1.y+e1.y+d1.y)*0.25f;
            v1.z = (a1.z+b1.z+e1.z+d1.z)*0.25f; v1.w = (a1.w+b1.w+e1.w+d1.w)*0.25f;
            sp[r0 * 8 + (cc0 ^ (r0 & 7))] = v0;
            sp[r1 * 8 + (cc1 ^ (r1 & 7))] = v1;
        }
        __syncwarp();
        {
            const int sw = t & 7;
            float4* row = &sp[t * 8];
            float u = 0.0f, s = 0.0f;
            #pragma unroll
            for (int c = 0; c < 8; c++) {
                float4 q = row[c ^ sw]; float4 v;
                u = u - s*th + q.x; s = (u > 0.0f) ? 1.0f : 0.0f; v.x = s;
                u = u - s*th + q.y; s = (u > 0.0f) ? 1.0f : 0.0f; v.y = s;
                u = u - s*th + q.z; s = (u > 0.0f) ? 1.0f : 0.0f; v.z = s;
                u = u - s*th + q.w; s = (u > 0.0f) ? 1.0f : 0.0f; v.w = s;
                row[c ^ sw] = v;
            }
        }
        __syncwarp();
        #pragma unroll
        for (int it = 0; it < 8; it++) {
            int cl = it * 32 + lane;
            int r = w * 32 + (cl >> 3), c = cl & 7;
            __stcs(ot + cl, sp[r * 8 + (c ^ (r & 7))]);
        }
        __syncthreads();
    }
}

extern "C" void kernel_launch(void* const* d_in, const int* in_sizes, int n_in,
                              void* d_out, int out_size)
{
    const float* x      = (const float*)d_in[0];
    const float* thresh = (const float*)d_in[1];
    float* out          = (float*)d_out;

    // Build TMA descriptor for out viewed as [NBLK*128 rows x 32 floats], SW128.
    typedef CUresult (*EncodeFn)(CUtensorMap*, CUtensorMapDataType, cuuint32_t, void*,
                                 const cuuint64_t*, const cuuint64_t*, const cuuint32_t*,
                                 const cuuint32_t*, CUtensorMapInterleave, CUtensorMapSwizzle,
                                 CUtensorMapL2promotion, CUtensorMapFloatOOBfill);
    void* fnp = nullptr;
    cudaDriverEntryPointQueryResult qr = cudaDriverEntryPointSymbolNotFound;
    cudaGetDriverEntryPointByVersion("cuTensorMapEncodeTiled", &fnp, 12000,
                                     cudaEnableDefault, &qr);
    bool ok = false;
    CUtensorMap tmap;
    if (fnp && qr == cudaDriverEntryPointSuccess) {
        cuuint64_t dims[2]    = {32, (cuuint64_t)NBLK * 128};
        cuuint64_t strides[1] = {128};                  // bytes between rows
        cuuint32_t box[2]     = {32, 128};              // 128B x 128 rows = 16KB
        cuuint32_t estr[2]    = {1, 1};
        CUresult r = ((EncodeFn)fnp)(&tmap, CU_TENSOR_MAP_DATA_TYPE_FLOAT32, 2, out,
                                     dims, strides, box, estr,
                                     CU_TENSOR_MAP_INTERLEAVE_NONE,
                                     CU_TENSOR_MAP_SWIZZLE_128B,
                                     CU_TENSOR_MAP_L2_PROMOTION_L2_128B,
                                     CU_TENSOR_MAP_FLOAT_OOB_FILL_NONE);
        ok = (r == CUDA_SUCCESS);
    }

    reset_ctr_kernel<<<1, 1>>>();
    if (ok)
        savgpool_spike_tma<<<GRIDSZ, 128>>>(x, thresh, tmap);
    else
        savgpool_spike_fb<<<GRIDSZ, 128>>>(x, thresh, out);
}